// round 11
// baseline (speedup 1.0000x reference)
#include <cuda_runtime.h>
#include <cuda_bf16.h>
#include <cuda_fp16.h>
#include <cstdint>
#include <cstddef>

#define NMAX 100000
#define EMAX 3200000
#define CH 128
#define CAP 64           // padded-CSR slots per node
#define OVF_CAP 65536

// ---------------- scratch ----------------
__device__ float  g_t[(size_t)NMAX * CH];       // t = x @ W_theta^T (fp32)
__device__ __half g_t_h[(size_t)NMAX * CH];     // fp16 copy for the min-gather
__device__ float  g_aggr[(size_t)NMAX * CH];
__device__ int    g_cur[NMAX];
__device__ int    g_csr[(size_t)NMAX * CAP];
__device__ int    g_novf;
__device__ int    g_ovf_r[OVF_CAP];
__device__ int    g_ovf_c[OVF_CAP];
__device__ __nv_bfloat16 g_w_hi[2 * CH * CH];
__device__ __nv_bfloat16 g_w_lo[2 * CH * CH];

// ---------------- init: zero counters + split W into bf16 hi/lo ----------------
__global__ void init_kernel(const float* __restrict__ Wt, const float* __restrict__ Wp, int n) {
    int i = blockIdx.x * blockDim.x + threadIdx.x;
    if (i < n) g_cur[i] = 0;
    if (i == 0) g_novf = 0;
    if (i < 2 * CH * CH) {
        float v = (i < CH * CH) ? Wt[i] : Wp[i - CH * CH];
        __nv_bfloat16 h = __float2bfloat16_rn(v);
        g_w_hi[i] = h;
        g_w_lo[i] = __float2bfloat16_rn(v - __bfloat162float(h));
    }
}

// ---------------- padded-CSR scatter (4 edges/thread) ----------------
__device__ __forceinline__ void push_edge(int r, int c) {
    int p = atomicAdd(&g_cur[r], 1);
    if (p < CAP) {
        g_csr[(size_t)r * CAP + p] = c;
    } else {
        int o = atomicAdd(&g_novf, 1);
        if (o < OVF_CAP) { g_ovf_r[o] = r; g_ovf_c[o] = c; }
    }
}

__global__ void scatter_kernel(const int* __restrict__ row, const int* __restrict__ col, int E) {
    int t = blockIdx.x * blockDim.x + threadIdx.x;
    int e0 = t * 4;
    if (e0 >= E) return;
    if (((E & 3) == 0) && (e0 + 4 <= E)) {
        int4 r4 = *reinterpret_cast<const int4*>(row + e0);
        int4 c4 = *reinterpret_cast<const int4*>(col + e0);
        push_edge(r4.x, c4.x);
        push_edge(r4.y, c4.y);
        push_edge(r4.z, c4.z);
        push_edge(r4.w, c4.w);
    } else {
        int lim = min(e0 + 4, E);
        for (int e = e0; e < lim; e++) push_edge(row[e], col[e]);
    }
}

// ---------------- HMMA helpers ----------------
__device__ __forceinline__ uint32_t smem_u32(const void* p) {
    uint32_t a;
    asm("{ .reg .u64 t; cvta.to.shared.u64 t, %1; cvt.u32.u64 %0, t; }" : "=r"(a) : "l"(p));
    return a;
}

__device__ __forceinline__ void ldsm_x4(uint32_t addr, uint32_t& r0, uint32_t& r1,
                                        uint32_t& r2, uint32_t& r3) {
    asm volatile("ldmatrix.sync.aligned.m8n8.x4.shared.b16 {%0,%1,%2,%3}, [%4];"
                 : "=r"(r0), "=r"(r1), "=r"(r2), "=r"(r3) : "r"(addr));
}

__device__ __forceinline__ void mma_bf16(float* c, const uint32_t* a, const uint32_t* b) {
    asm volatile(
        "mma.sync.aligned.m16n8k16.row.col.f32.bf16.bf16.f32 "
        "{%0,%1,%2,%3}, {%4,%5,%6,%7}, {%8,%9}, {%0,%1,%2,%3};"
        : "+f"(c[0]), "+f"(c[1]), "+f"(c[2]), "+f"(c[3])
        : "r"(a[0]), "r"(a[1]), "r"(a[2]), "r"(a[3]), "r"(b[0]), "r"(b[1]));
}

// ---------------- tensor-core GEMM: C[M,128] = A[M,128] @ W^T ----------------
// bf16 hi/lo split, 3 accumulating passes: Ahi*Whi + Ahi*Wlo + Alo*Whi.
// m_off: node offset of this launch's first row (for chunked launches).
#define ROWB 272
#define TILEB (128 * ROWB)
#define AS_HI 0
#define AS_LO TILEB
#define WS_HI (2 * TILEB)
#define WS_LO (3 * TILEB)
#define GSM_TOTAL (4 * TILEB)

__device__ __forceinline__ void split_bf16(float v, __nv_bfloat16& h, __nv_bfloat16& l) {
    h = __float2bfloat16_rn(v);
    l = __float2bfloat16_rn(v - __bfloat162float(h));
}

__global__ __launch_bounds__(256) void tc_gemm_kernel(
    const float* __restrict__ A, float* __restrict__ C, __half* __restrict__ Ch,
    int M, int which, int m_off)
{
    extern __shared__ char smem[];
    const uint32_t sb = smem_u32(smem);
    const int tid = threadIdx.x;
    const int w = tid >> 5;
    const int lane = tid & 31;
    const int m0 = m_off + blockIdx.x * 128;

    // stage A: fp32 -> bf16 hi/lo
    #pragma unroll
    for (int it = 0; it < 16; it++) {
        int q = tid + it * 256;
        int r = q >> 5;
        int c4 = q & 31;
        int gm = m0 + r;
        float4 v = make_float4(0.f, 0.f, 0.f, 0.f);
        if (gm < M) v = *reinterpret_cast<const float4*>(A + (size_t)gm * CH + c4 * 4);

        __nv_bfloat16 h0, h1, h2, h3, l0, l1, l2, l3;
        split_bf16(v.x, h0, l0); split_bf16(v.y, h1, l1);
        split_bf16(v.z, h2, l2); split_bf16(v.w, h3, l3);

        uint32_t hw0 = ((uint32_t)__bfloat16_as_ushort(h1) << 16) | __bfloat16_as_ushort(h0);
        uint32_t hw1 = ((uint32_t)__bfloat16_as_ushort(h3) << 16) | __bfloat16_as_ushort(h2);
        uint32_t lw0 = ((uint32_t)__bfloat16_as_ushort(l1) << 16) | __bfloat16_as_ushort(l0);
        uint32_t lw1 = ((uint32_t)__bfloat16_as_ushort(l3) << 16) | __bfloat16_as_ushort(l2);

        int off = r * ROWB + c4 * 8;
        *reinterpret_cast<uint2*>(smem + AS_HI + off) = make_uint2(hw0, hw1);
        *reinterpret_cast<uint2*>(smem + AS_LO + off) = make_uint2(lw0, lw1);
    }

    // stage W hi/lo
    const uint4* whi = reinterpret_cast<const uint4*>(g_w_hi + (size_t)which * CH * CH);
    const uint4* wlo = reinterpret_cast<const uint4*>(g_w_lo + (size_t)which * CH * CH);
    #pragma unroll
    for (int it = 0; it < 8; it++) {
        int q = tid + it * 256;
        int r = q >> 4;
        int u = q & 15;
        int off = r * ROWB + u * 16;
        *reinterpret_cast<uint4*>(smem + WS_HI + off) = whi[q];
        *reinterpret_cast<uint4*>(smem + WS_LO + off) = wlo[q];
    }
    __syncthreads();

    // compute: warp grid 4(M) x 2(N); warp tile 32x64
    const int mw0 = (w & 3) * 32;
    const int nw0 = (w >> 2) * 64;

    float acc[2][8][4];
    #pragma unroll
    for (int i = 0; i < 2; i++)
        #pragma unroll
        for (int j = 0; j < 8; j++)
            #pragma unroll
            for (int q = 0; q < 4; q++) acc[i][j][q] = 0.f;

    const int a_row = mw0 + (lane & 15);
    const int a_kof = (lane >> 4) * 8;
    const int b_nof = (lane & 7) + ((lane >> 4) ? 8 : 0);
    const int b_kof = ((lane >> 3) & 1) * 8;

    const uint32_t a_base0 = sb + a_row * ROWB + a_kof * 2;
    const uint32_t b_base0 = sb + (nw0 + b_nof) * ROWB + b_kof * 2;

    #pragma unroll
    for (int pass = 0; pass < 3; pass++) {
        const uint32_t a_base = a_base0 + ((pass < 2) ? AS_HI : AS_LO);
        const uint32_t b_base = b_base0 + ((pass == 1) ? WS_LO : WS_HI);
        #pragma unroll
        for (int ks = 0; ks < 8; ks++) {
            const int k0 = ks * 16;
            uint32_t af[2][4];
            ldsm_x4(a_base + k0 * 2,             af[0][0], af[0][1], af[0][2], af[0][3]);
            ldsm_x4(a_base + 16 * ROWB + k0 * 2, af[1][0], af[1][1], af[1][2], af[1][3]);
            uint32_t bf[8][2];
            #pragma unroll
            for (int p = 0; p < 4; p++) {
                uint32_t r0, r1, r2, r3;
                ldsm_x4(b_base + p * 16 * ROWB + k0 * 2, r0, r1, r2, r3);
                bf[2 * p][0] = r0; bf[2 * p][1] = r1;
                bf[2 * p + 1][0] = r2; bf[2 * p + 1][1] = r3;
            }
            #pragma unroll
            for (int i = 0; i < 2; i++)
                #pragma unroll
                for (int j = 0; j < 8; j++)
                    mma_bf16(acc[i][j], af[i], bf[j]);
        }
    }

    // epilogue (+ optional fp16 mirror)
    const int mq = lane >> 2;
    const int nq = (lane & 3) * 2;
    #pragma unroll
    for (int i = 0; i < 2; i++) {
        #pragma unroll
        for (int half = 0; half < 2; half++) {
            int gm = m0 + mw0 + i * 16 + mq + half * 8;
            if (gm < M) {
                #pragma unroll
                for (int j = 0; j < 8; j++) {
                    float2 o = half ? make_float2(acc[i][j][2], acc[i][j][3])
                                    : make_float2(acc[i][j][0], acc[i][j][1]);
                    *reinterpret_cast<float2*>(C + (size_t)gm * CH + nw0 + j * 8 + nq) = o;
                    if (Ch) {
                        __half2 h = __float22half2_rn(o);
                        *reinterpret_cast<__half2*>(Ch + (size_t)gm * CH + nw0 + j * 8 + nq) = h;
                    }
                }
            }
        }
    }
}

// ---------------- aggr: warp-per-node; aggr[n] = t[n] - min_nbr t_h[col] ----------------
// n_off/n_cnt: node range of this launch (for chunked launches).
__global__ __launch_bounds__(256) void aggr_kernel(int n_off, int n_cnt) {
    const int gw = (blockIdx.x * blockDim.x + threadIdx.x) >> 5;
    if (gw >= n_cnt) return;
    const int n = n_off + gw;
    const int lane = threadIdx.x & 31;
    const int cnt = min(g_cur[n], CAP);

    const __half2 hbig = __float2half2_rn(60000.f);
    __half2 a0 = hbig, a1 = hbig;
    __half2 b0 = hbig, b1 = hbig;

    const size_t csr_base = (size_t)n * CAP;

    for (int base = 0; base < cnt; base += 32) {
        int my_col = (base + lane < cnt) ? g_csr[csr_base + base + lane] : 0;
        int lim = min(32, cnt - base);
        int j = 0;
        #pragma unroll 4
        for (; j + 2 <= lim; j += 2) {
            int c0 = __shfl_sync(0xffffffffu, my_col, j);
            int c1 = __shfl_sync(0xffffffffu, my_col, j + 1);
            uint2 v0 = *reinterpret_cast<const uint2*>(g_t_h + (size_t)c0 * CH + lane * 4);
            uint2 v1 = *reinterpret_cast<const uint2*>(g_t_h + (size_t)c1 * CH + lane * 4);
            a0 = __hmin2(a0, *reinterpret_cast<const __half2*>(&v0.x));
            a1 = __hmin2(a1, *reinterpret_cast<const __half2*>(&v0.y));
            b0 = __hmin2(b0, *reinterpret_cast<const __half2*>(&v1.x));
            b1 = __hmin2(b1, *reinterpret_cast<const __half2*>(&v1.y));
        }
        if (j < lim) {
            int c0 = __shfl_sync(0xffffffffu, my_col, j);
            uint2 v0 = *reinterpret_cast<const uint2*>(g_t_h + (size_t)c0 * CH + lane * 4);
            a0 = __hmin2(a0, *reinterpret_cast<const __half2*>(&v0.x));
            a1 = __hmin2(a1, *reinterpret_cast<const __half2*>(&v0.y));
        }
    }

    // overflow spill (empty in practice; correct for any input)
    int novf = g_novf;
    for (int i = 0; i < novf; i++) {
        if (g_ovf_r[i] == n) {
            uint2 v = *reinterpret_cast<const uint2*>(g_t_h + (size_t)g_ovf_c[i] * CH + lane * 4);
            a0 = __hmin2(a0, *reinterpret_cast<const __half2*>(&v.x));
            a1 = __hmin2(a1, *reinterpret_cast<const __half2*>(&v.y));
        }
    }

    a0 = __hmin2(a0, b0);
    a1 = __hmin2(a1, b1);

    float4 outv;
    if (cnt == 0) {
        outv = make_float4(0.f, 0.f, 0.f, 0.f);
    } else {
        const float4 tv = *reinterpret_cast<const float4*>(g_t + (size_t)n * CH + lane * 4);
        outv = make_float4(tv.x - __low2float(a0), tv.y - __high2float(a0),
                           tv.z - __low2float(a1), tv.w - __high2float(a1));
    }
    *reinterpret_cast<float4*>(g_aggr + (size_t)n * CH + lane * 4) = outv;
}

// ---------------- launch: scatter||gemm1, then chunked aggr->gemm2 pipeline ----------------
#define NCHUNK 4

extern "C" void kernel_launch(void* const* d_in, const int* in_sizes, int n_in,
                              void* d_out, int out_size) {
    const float* x  = (const float*)d_in[0];
    const int*   ei = (const int*)d_in[1];
    const float* Wt = (const float*)d_in[2];
    const float* Wp = (const float*)d_in[3];
    float* out = (float*)d_out;

    int N = in_sizes[0] / CH;
    int E = in_sizes[1] / 2;
    const int* row = ei;
    const int* col = ei + E;
    int ngb = (N + 127) / 128;

    void *pt = nullptr, *pth = nullptr, *pa = nullptr;
    cudaGetSymbolAddress(&pt, g_t);
    cudaGetSymbolAddress(&pth, g_t_h);
    cudaGetSymbolAddress(&pa, g_aggr);

    cudaFuncSetAttribute(tc_gemm_kernel, cudaFuncAttributeMaxDynamicSharedMemorySize, GSM_TOTAL);

    cudaStream_t s1;
    cudaStreamCreateWithFlags(&s1, cudaStreamNonBlocking);
    cudaEvent_t e_fork, e_join, e_chunk[NCHUNK], e_done;
    cudaEventCreateWithFlags(&e_fork, cudaEventDisableTiming);
    cudaEventCreateWithFlags(&e_join, cudaEventDisableTiming);
    cudaEventCreateWithFlags(&e_done, cudaEventDisableTiming);
    for (int k = 0; k < NCHUNK; k++)
        cudaEventCreateWithFlags(&e_chunk[k], cudaEventDisableTiming);

    // init on default stream (zeroes g_cur, splits W)
    init_kernel<<<(N + 255) / 256, 256>>>(Wt, Wp, N);

    // fork: scatter on s1, gemm1 on default
    cudaEventRecord(e_fork, 0);
    cudaStreamWaitEvent(s1, e_fork, 0);
    scatter_kernel<<<((E + 3) / 4 + 255) / 256, 256, 0, s1>>>(row, col, E);
    tc_gemm_kernel<<<ngb, 256, GSM_TOTAL>>>(x, (float*)pt, (__half*)pth, N, 0, 0);

    // join: default stream waits for scatter before aggr starts
    cudaEventRecord(e_join, s1);
    cudaStreamWaitEvent(0, e_join, 0);

    // chunked aggr (stream 0) -> gemm2 (stream s1) pipeline
    int blk_per_chunk = (ngb + NCHUNK - 1) / NCHUNK;   // blocks of 128 rows
    for (int k = 0; k < NCHUNK; k++) {
        int b0 = k * blk_per_chunk;
        if (b0 >= ngb) break;
        int nb = min(blk_per_chunk, ngb - b0);
        int n_off = b0 * 128;
        int n_cnt = min(nb * 128, N - n_off);

        aggr_kernel<<<(n_cnt * 32 + 255) / 256, 256>>>(n_off, n_cnt);
        cudaEventRecord(e_chunk[k], 0);
        cudaStreamWaitEvent(s1, e_chunk[k], 0);
        tc_gemm_kernel<<<nb, 256, GSM_TOTAL, s1>>>((const float*)pa, out, nullptr, N, 1, n_off);
    }

    // join gemm2 stream back to default
    cudaEventRecord(e_done, s1);
    cudaStreamWaitEvent(0, e_done, 0);

    for (int k = 0; k < NCHUNK; k++) cudaEventDestroy(e_chunk[k]);
    cudaEventDestroy(e_fork);
    cudaEventDestroy(e_join);
    cudaEventDestroy(e_done);
    cudaStreamDestroy(s1);
}

// round 12
// speedup vs baseline: 1.1259x; 1.1259x over previous
#include <cuda_runtime.h>
#include <cuda_bf16.h>
#include <cuda_fp16.h>
#include <cstdint>
#include <cstddef>

#define NMAX 100000
#define EMAX 3200000
#define CH 128
#define CAP 64           // padded-CSR slots per node
#define OVF_CAP 65536

// ---------------- scratch ----------------
__device__ __half g_t_h[(size_t)NMAX * CH];     // t = x @ W_theta^T (fp16 only)
__device__ float  g_aggr[(size_t)NMAX * CH];
__device__ int    g_cur[NMAX];
__device__ int    g_csr[(size_t)NMAX * CAP];
__device__ int    g_novf;
__device__ int    g_ovf_r[OVF_CAP];
__device__ int    g_ovf_c[OVF_CAP];
__device__ __nv_bfloat16 g_w_hi[2 * CH * CH];
__device__ __nv_bfloat16 g_w_lo[2 * CH * CH];

// ---------------- init: zero counters + split W into bf16 hi/lo ----------------
__global__ void init_kernel(const float* __restrict__ Wt, const float* __restrict__ Wp, int n) {
    int i = blockIdx.x * blockDim.x + threadIdx.x;
    if (i < n) g_cur[i] = 0;
    if (i == 0) g_novf = 0;
    if (i < 2 * CH * CH) {
        float v = (i < CH * CH) ? Wt[i] : Wp[i - CH * CH];
        __nv_bfloat16 h = __float2bfloat16_rn(v);
        g_w_hi[i] = h;
        g_w_lo[i] = __float2bfloat16_rn(v - __bfloat162float(h));
    }
}

// ---------------- padded-CSR scatter (4 edges/thread) ----------------
__device__ __forceinline__ void push_edge(int r, int c) {
    int p = atomicAdd(&g_cur[r], 1);
    if (p < CAP) {
        g_csr[(size_t)r * CAP + p] = c;
    } else {
        int o = atomicAdd(&g_novf, 1);
        if (o < OVF_CAP) { g_ovf_r[o] = r; g_ovf_c[o] = c; }
    }
}

__global__ void scatter_kernel(const int* __restrict__ row, const int* __restrict__ col, int E) {
    int t = blockIdx.x * blockDim.x + threadIdx.x;
    int e0 = t * 4;
    if (e0 >= E) return;
    if (((E & 3) == 0) && (e0 + 4 <= E)) {
        int4 r4 = *reinterpret_cast<const int4*>(row + e0);
        int4 c4 = *reinterpret_cast<const int4*>(col + e0);
        push_edge(r4.x, c4.x);
        push_edge(r4.y, c4.y);
        push_edge(r4.z, c4.z);
        push_edge(r4.w, c4.w);
    } else {
        int lim = min(e0 + 4, E);
        for (int e = e0; e < lim; e++) push_edge(row[e], col[e]);
    }
}

// ---------------- HMMA helpers ----------------
__device__ __forceinline__ uint32_t smem_u32(const void* p) {
    uint32_t a;
    asm("{ .reg .u64 t; cvta.to.shared.u64 t, %1; cvt.u32.u64 %0, t; }" : "=r"(a) : "l"(p));
    return a;
}

__device__ __forceinline__ void ldsm_x4(uint32_t addr, uint32_t& r0, uint32_t& r1,
                                        uint32_t& r2, uint32_t& r3) {
    asm volatile("ldmatrix.sync.aligned.m8n8.x4.shared.b16 {%0,%1,%2,%3}, [%4];"
                 : "=r"(r0), "=r"(r1), "=r"(r2), "=r"(r3) : "r"(addr));
}

__device__ __forceinline__ void mma_bf16(float* c, const uint32_t* a, const uint32_t* b) {
    asm volatile(
        "mma.sync.aligned.m16n8k16.row.col.f32.bf16.bf16.f32 "
        "{%0,%1,%2,%3}, {%4,%5,%6,%7}, {%8,%9}, {%0,%1,%2,%3};"
        : "+f"(c[0]), "+f"(c[1]), "+f"(c[2]), "+f"(c[3])
        : "r"(a[0]), "r"(a[1]), "r"(a[2]), "r"(a[3]), "r"(b[0]), "r"(b[1]));
}

// ---------------- tensor-core GEMM: C[M,128] = A[M,128] @ W^T ----------------
// bf16 hi/lo split, 3 accumulating passes: Ahi*Whi + Ahi*Wlo + Alo*Whi.
// Writes fp32 to C (if non-null) and/or fp16 to Ch (if non-null).
#define ROWB 272
#define TILEB (128 * ROWB)
#define AS_HI 0
#define AS_LO TILEB
#define WS_HI (2 * TILEB)
#define WS_LO (3 * TILEB)
#define GSM_TOTAL (4 * TILEB)

__device__ __forceinline__ void split_bf16(float v, __nv_bfloat16& h, __nv_bfloat16& l) {
    h = __float2bfloat16_rn(v);
    l = __float2bfloat16_rn(v - __bfloat162float(h));
}

__global__ __launch_bounds__(256) void tc_gemm_kernel(
    const float* __restrict__ A, float* __restrict__ C, __half* __restrict__ Ch,
    int M, int which)
{
    extern __shared__ char smem[];
    const uint32_t sb = smem_u32(smem);
    const int tid = threadIdx.x;
    const int w = tid >> 5;
    const int lane = tid & 31;
    const int m0 = blockIdx.x * 128;

    // stage A: fp32 -> bf16 hi/lo
    #pragma unroll
    for (int it = 0; it < 16; it++) {
        int q = tid + it * 256;
        int r = q >> 5;
        int c4 = q & 31;
        int gm = m0 + r;
        float4 v = make_float4(0.f, 0.f, 0.f, 0.f);
        if (gm < M) v = *reinterpret_cast<const float4*>(A + (size_t)gm * CH + c4 * 4);

        __nv_bfloat16 h0, h1, h2, h3, l0, l1, l2, l3;
        split_bf16(v.x, h0, l0); split_bf16(v.y, h1, l1);
        split_bf16(v.z, h2, l2); split_bf16(v.w, h3, l3);

        uint32_t hw0 = ((uint32_t)__bfloat16_as_ushort(h1) << 16) | __bfloat16_as_ushort(h0);
        uint32_t hw1 = ((uint32_t)__bfloat16_as_ushort(h3) << 16) | __bfloat16_as_ushort(h2);
        uint32_t lw0 = ((uint32_t)__bfloat16_as_ushort(l1) << 16) | __bfloat16_as_ushort(l0);
        uint32_t lw1 = ((uint32_t)__bfloat16_as_ushort(l3) << 16) | __bfloat16_as_ushort(l2);

        int off = r * ROWB + c4 * 8;
        *reinterpret_cast<uint2*>(smem + AS_HI + off) = make_uint2(hw0, hw1);
        *reinterpret_cast<uint2*>(smem + AS_LO + off) = make_uint2(lw0, lw1);
    }

    // stage W hi/lo
    const uint4* whi = reinterpret_cast<const uint4*>(g_w_hi + (size_t)which * CH * CH);
    const uint4* wlo = reinterpret_cast<const uint4*>(g_w_lo + (size_t)which * CH * CH);
    #pragma unroll
    for (int it = 0; it < 8; it++) {
        int q = tid + it * 256;
        int r = q >> 4;
        int u = q & 15;
        int off = r * ROWB + u * 16;
        *reinterpret_cast<uint4*>(smem + WS_HI + off) = whi[q];
        *reinterpret_cast<uint4*>(smem + WS_LO + off) = wlo[q];
    }
    __syncthreads();

    // compute: warp grid 4(M) x 2(N); warp tile 32x64
    const int mw0 = (w & 3) * 32;
    const int nw0 = (w >> 2) * 64;

    float acc[2][8][4];
    #pragma unroll
    for (int i = 0; i < 2; i++)
        #pragma unroll
        for (int j = 0; j < 8; j++)
            #pragma unroll
            for (int q = 0; q < 4; q++) acc[i][j][q] = 0.f;

    const int a_row = mw0 + (lane & 15);
    const int a_kof = (lane >> 4) * 8;
    const int b_nof = (lane & 7) + ((lane >> 4) ? 8 : 0);
    const int b_kof = ((lane >> 3) & 1) * 8;

    const uint32_t a_base0 = sb + a_row * ROWB + a_kof * 2;
    const uint32_t b_base0 = sb + (nw0 + b_nof) * ROWB + b_kof * 2;

    #pragma unroll
    for (int pass = 0; pass < 3; pass++) {
        const uint32_t a_base = a_base0 + ((pass < 2) ? AS_HI : AS_LO);
        const uint32_t b_base = b_base0 + ((pass == 1) ? WS_LO : WS_HI);
        #pragma unroll
        for (int ks = 0; ks < 8; ks++) {
            const int k0 = ks * 16;
            uint32_t af[2][4];
            ldsm_x4(a_base + k0 * 2,             af[0][0], af[0][1], af[0][2], af[0][3]);
            ldsm_x4(a_base + 16 * ROWB + k0 * 2, af[1][0], af[1][1], af[1][2], af[1][3]);
            uint32_t bf[8][2];
            #pragma unroll
            for (int p = 0; p < 4; p++) {
                uint32_t r0, r1, r2, r3;
                ldsm_x4(b_base + p * 16 * ROWB + k0 * 2, r0, r1, r2, r3);
                bf[2 * p][0] = r0; bf[2 * p][1] = r1;
                bf[2 * p + 1][0] = r2; bf[2 * p + 1][1] = r3;
            }
            #pragma unroll
            for (int i = 0; i < 2; i++)
                #pragma unroll
                for (int j = 0; j < 8; j++)
                    mma_bf16(acc[i][j], af[i], bf[j]);
        }
    }

    // epilogue: fp32 (C) and/or fp16 (Ch)
    const int mq = lane >> 2;
    const int nq = (lane & 3) * 2;
    #pragma unroll
    for (int i = 0; i < 2; i++) {
        #pragma unroll
        for (int half = 0; half < 2; half++) {
            int gm = m0 + mw0 + i * 16 + mq + half * 8;
            if (gm < M) {
                #pragma unroll
                for (int j = 0; j < 8; j++) {
                    float2 o = half ? make_float2(acc[i][j][2], acc[i][j][3])
                                    : make_float2(acc[i][j][0], acc[i][j][1]);
                    if (C)
                        *reinterpret_cast<float2*>(C + (size_t)gm * CH + nw0 + j * 8 + nq) = o;
                    if (Ch) {
                        __half2 h = __float22half2_rn(o);
                        *reinterpret_cast<__half2*>(Ch + (size_t)gm * CH + nw0 + j * 8 + nq) = h;
                    }
                }
            }
        }
    }
}

// ---------------- aggr: warp-per-node; aggr[n] = t_h[n] - min_nbr t_h[col] ----------------
__global__ __launch_bounds__(256) void aggr_kernel(int N) {
    const int gw = (blockIdx.x * blockDim.x + threadIdx.x) >> 5;
    if (gw >= N) return;
    const int n = gw;
    const int lane = threadIdx.x & 31;
    const int cnt = min(g_cur[n], CAP);

    const __half2 hbig = __float2half2_rn(60000.f);
    __half2 a0 = hbig, a1 = hbig;
    __half2 b0 = hbig, b1 = hbig;

    const size_t csr_base = (size_t)n * CAP;

    for (int base = 0; base < cnt; base += 32) {
        int my_col = (base + lane < cnt) ? g_csr[csr_base + base + lane] : 0;
        int lim = min(32, cnt - base);
        int j = 0;
        #pragma unroll 4
        for (; j + 2 <= lim; j += 2) {
            int c0 = __shfl_sync(0xffffffffu, my_col, j);
            int c1 = __shfl_sync(0xffffffffu, my_col, j + 1);
            uint2 v0 = *reinterpret_cast<const uint2*>(g_t_h + (size_t)c0 * CH + lane * 4);
            uint2 v1 = *reinterpret_cast<const uint2*>(g_t_h + (size_t)c1 * CH + lane * 4);
            a0 = __hmin2(a0, *reinterpret_cast<const __half2*>(&v0.x));
            a1 = __hmin2(a1, *reinterpret_cast<const __half2*>(&v0.y));
            b0 = __hmin2(b0, *reinterpret_cast<const __half2*>(&v1.x));
            b1 = __hmin2(b1, *reinterpret_cast<const __half2*>(&v1.y));
        }
        if (j < lim) {
            int c0 = __shfl_sync(0xffffffffu, my_col, j);
            uint2 v0 = *reinterpret_cast<const uint2*>(g_t_h + (size_t)c0 * CH + lane * 4);
            a0 = __hmin2(a0, *reinterpret_cast<const __half2*>(&v0.x));
            a1 = __hmin2(a1, *reinterpret_cast<const __half2*>(&v0.y));
        }
    }

    // overflow spill (empty in practice; correct for any input)
    int novf = g_novf;
    for (int i = 0; i < novf; i++) {
        if (g_ovf_r[i] == n) {
            uint2 v = *reinterpret_cast<const uint2*>(g_t_h + (size_t)g_ovf_c[i] * CH + lane * 4);
            a0 = __hmin2(a0, *reinterpret_cast<const __half2*>(&v.x));
            a1 = __hmin2(a1, *reinterpret_cast<const __half2*>(&v.y));
        }
    }

    a0 = __hmin2(a0, b0);
    a1 = __hmin2(a1, b1);

    float4 outv;
    if (cnt == 0) {
        outv = make_float4(0.f, 0.f, 0.f, 0.f);
    } else {
        uint2 tv = *reinterpret_cast<const uint2*>(g_t_h + (size_t)n * CH + lane * 4);
        const __half2 t0 = *reinterpret_cast<const __half2*>(&tv.x);
        const __half2 t1 = *reinterpret_cast<const __half2*>(&tv.y);
        outv = make_float4(__low2float(t0) - __low2float(a0),
                           __high2float(t0) - __high2float(a0),
                           __low2float(t1) - __low2float(a1),
                           __high2float(t1) - __high2float(a1));
    }
    *reinterpret_cast<float4*>(g_aggr + (size_t)n * CH + lane * 4) = outv;
}

// ---------------- launch: fork-join streams (scatter || gemm1) ----------------
extern "C" void kernel_launch(void* const* d_in, const int* in_sizes, int n_in,
                              void* d_out, int out_size) {
    const float* x  = (const float*)d_in[0];
    const int*   ei = (const int*)d_in[1];
    const float* Wt = (const float*)d_in[2];
    const float* Wp = (const float*)d_in[3];
    float* out = (float*)d_out;

    int N = in_sizes[0] / CH;
    int E = in_sizes[1] / 2;
    const int* row = ei;
    const int* col = ei + E;
    int ngb = (N + 127) / 128;

    void *pth = nullptr, *pa = nullptr;
    cudaGetSymbolAddress(&pth, g_t_h);
    cudaGetSymbolAddress(&pa, g_aggr);

    cudaFuncSetAttribute(tc_gemm_kernel, cudaFuncAttributeMaxDynamicSharedMemorySize, GSM_TOTAL);

    cudaStream_t s1;
    cudaStreamCreateWithFlags(&s1, cudaStreamNonBlocking);
    cudaEvent_t e_fork, e_join;
    cudaEventCreateWithFlags(&e_fork, cudaEventDisableTiming);
    cudaEventCreateWithFlags(&e_join, cudaEventDisableTiming);

    // init on default stream (zeroes g_cur, splits W)
    init_kernel<<<(N + 255) / 256, 256>>>(Wt, Wp, N);

    // fork: scatter on s1, gemm1 on default
    cudaEventRecord(e_fork, 0);
    cudaStreamWaitEvent(s1, e_fork, 0);
    scatter_kernel<<<((E + 3) / 4 + 255) / 256, 256, 0, s1>>>(row, col, E);
    tc_gemm_kernel<<<ngb, 256, GSM_TOTAL>>>(x, nullptr, (__half*)pth, N, 0);

    // join: default stream waits for scatter
    cudaEventRecord(e_join, s1);
    cudaStreamWaitEvent(0, e_join, 0);

    aggr_kernel<<<(N * 32 + 255) / 256, 256>>>(N);
    tc_gemm_kernel<<<ngb, 256, GSM_TOTAL>>>((const float*)pa, out, nullptr, N, 1);

    cudaEventDestroy(e_fork);
    cudaEventDestroy(e_join);
    cudaStreamDestroy(s1);
}

// round 13
// speedup vs baseline: 1.3569x; 1.2052x over previous
#include <cuda_runtime.h>
#include <cuda_fp16.h>
#include <cstdint>
#include <cstddef>

#define NMAX 100000
#define EMAX 3200000
#define CH 128
#define CAP 64           // padded-CSR slots per node
#define OVF_CAP 65536

// ---------------- scratch ----------------
__device__ __half g_t_h[(size_t)NMAX * CH];     // t = x @ W_theta^T (fp16)
__device__ __half g_aggr_h[(size_t)NMAX * CH];  // aggr output (fp16)
__device__ int    g_cur[NMAX];
__device__ int    g_csr[(size_t)NMAX * CAP];
__device__ int    g_novf;
__device__ int    g_ovf_r[OVF_CAP];
__device__ int    g_ovf_c[OVF_CAP];
__device__ __half g_w_hi[2 * CH * CH];          // fp16 hi part of W
__device__ __half g_w_lo[2 * CH * CH];          // fp16 lo residual of W

// ---------------- init: zero counters + split W into fp16 hi/lo ----------------
__global__ void init_kernel(const float* __restrict__ Wt, const float* __restrict__ Wp, int n) {
    int i = blockIdx.x * blockDim.x + threadIdx.x;
    if (i < n) g_cur[i] = 0;
    if (i == 0) g_novf = 0;
    if (i < 2 * CH * CH) {
        float v = (i < CH * CH) ? Wt[i] : Wp[i - CH * CH];
        __half h = __float2half_rn(v);
        g_w_hi[i] = h;
        g_w_lo[i] = __float2half_rn(v - __half2float(h));
    }
}

// ---------------- padded-CSR scatter (4 edges/thread) ----------------
__device__ __forceinline__ void push_edge(int r, int c) {
    int p = atomicAdd(&g_cur[r], 1);
    if (p < CAP) {
        g_csr[(size_t)r * CAP + p] = c;
    } else {
        int o = atomicAdd(&g_novf, 1);
        if (o < OVF_CAP) { g_ovf_r[o] = r; g_ovf_c[o] = c; }
    }
}

__global__ void scatter_kernel(const int* __restrict__ row, const int* __restrict__ col, int E) {
    int t = blockIdx.x * blockDim.x + threadIdx.x;
    int e0 = t * 4;
    if (e0 >= E) return;
    if (((E & 3) == 0) && (e0 + 4 <= E)) {
        int4 r4 = *reinterpret_cast<const int4*>(row + e0);
        int4 c4 = *reinterpret_cast<const int4*>(col + e0);
        push_edge(r4.x, c4.x);
        push_edge(r4.y, c4.y);
        push_edge(r4.z, c4.z);
        push_edge(r4.w, c4.w);
    } else {
        int lim = min(e0 + 4, E);
        for (int e = e0; e < lim; e++) push_edge(row[e], col[e]);
    }
}

// ---------------- HMMA helpers ----------------
__device__ __forceinline__ uint32_t smem_u32(const void* p) {
    uint32_t a;
    asm("{ .reg .u64 t; cvta.to.shared.u64 t, %1; cvt.u32.u64 %0, t; }" : "=r"(a) : "l"(p));
    return a;
}

__device__ __forceinline__ void ldsm_x4(uint32_t addr, uint32_t& r0, uint32_t& r1,
                                        uint32_t& r2, uint32_t& r3) {
    asm volatile("ldmatrix.sync.aligned.m8n8.x4.shared.b16 {%0,%1,%2,%3}, [%4];"
                 : "=r"(r0), "=r"(r1), "=r"(r2), "=r"(r3) : "r"(addr));
}

__device__ __forceinline__ void mma_f16(float* c, const uint32_t* a, const uint32_t* b) {
    asm volatile(
        "mma.sync.aligned.m16n8k16.row.col.f32.f16.f16.f32 "
        "{%0,%1,%2,%3}, {%4,%5,%6,%7}, {%8,%9}, {%0,%1,%2,%3};"
        : "+f"(c[0]), "+f"(c[1]), "+f"(c[2]), "+f"(c[3])
        : "r"(a[0]), "r"(a[1]), "r"(a[2]), "r"(a[3]), "r"(b[0]), "r"(b[1]));
}

// ---------------- tensor-core GEMM: C[M,128] = A[M,128] @ W^T ----------------
// fp16 operands, W split into fp16 hi/lo, 2 accumulating passes: A*Wh + A*Wl.
// A tile single fp16 copy; SMEM 3 tiles -> 2 CTAs/SM.
#define ROWB 272
#define TILEB (128 * ROWB)
#define AS_T  0
#define WS_HI TILEB
#define WS_LO (2 * TILEB)
#define GSM_TOTAL (3 * TILEB)     // 104448

// A source mode: 0 = fp32 gmem (convert), 1 = fp16 gmem (direct copy)
__global__ __launch_bounds__(256, 2) void tc_gemm_kernel(
    const float* __restrict__ A32, const __half* __restrict__ A16,
    float* __restrict__ C, __half* __restrict__ Ch,
    int M, int which)
{
    extern __shared__ char smem[];
    const uint32_t sb = smem_u32(smem);
    const int tid = threadIdx.x;
    const int w = tid >> 5;
    const int lane = tid & 31;
    const int m0 = blockIdx.x * 128;

    // stage A -> fp16 smem tile
    if (A32) {
        #pragma unroll
        for (int it = 0; it < 16; it++) {
            int q = tid + it * 256;          // 0..4095 float4s
            int r = q >> 5;
            int c4 = q & 31;
            int gm = m0 + r;
            float4 v = make_float4(0.f, 0.f, 0.f, 0.f);
            if (gm < M) v = *reinterpret_cast<const float4*>(A32 + (size_t)gm * CH + c4 * 4);
            __half2 h01 = __float22half2_rn(make_float2(v.x, v.y));
            __half2 h23 = __float22half2_rn(make_float2(v.z, v.w));
            int off = r * ROWB + c4 * 8;
            *reinterpret_cast<uint2*>(smem + AS_T + off) =
                make_uint2(*reinterpret_cast<uint32_t*>(&h01), *reinterpret_cast<uint32_t*>(&h23));
        }
    } else {
        #pragma unroll
        for (int it = 0; it < 8; it++) {
            int q = tid + it * 256;          // 0..2047 uint4s (16B = 8 halves)
            int r = q >> 4;
            int u = q & 15;
            int gm = m0 + r;
            uint4 v = make_uint4(0u, 0u, 0u, 0u);
            if (gm < M) v = *reinterpret_cast<const uint4*>(A16 + (size_t)gm * CH + u * 8);
            *reinterpret_cast<uint4*>(smem + AS_T + r * ROWB + u * 16) = v;
        }
    }

    // stage W hi/lo (fp16 in global)
    const uint4* whi = reinterpret_cast<const uint4*>(g_w_hi + (size_t)which * CH * CH);
    const uint4* wlo = reinterpret_cast<const uint4*>(g_w_lo + (size_t)which * CH * CH);
    #pragma unroll
    for (int it = 0; it < 8; it++) {
        int q = tid + it * 256;
        int r = q >> 4;
        int u = q & 15;
        int off = r * ROWB + u * 16;
        *reinterpret_cast<uint4*>(smem + WS_HI + off) = whi[q];
        *reinterpret_cast<uint4*>(smem + WS_LO + off) = wlo[q];
    }
    __syncthreads();

    // compute: warp grid 4(M) x 2(N); warp tile 32x64
    const int mw0 = (w & 3) * 32;
    const int nw0 = (w >> 2) * 64;

    float acc[2][8][4];
    #pragma unroll
    for (int i = 0; i < 2; i++)
        #pragma unroll
        for (int j = 0; j < 8; j++)
            #pragma unroll
            for (int q = 0; q < 4; q++) acc[i][j][q] = 0.f;

    const int a_row = mw0 + (lane & 15);
    const int a_kof = (lane >> 4) * 8;
    const int b_nof = (lane & 7) + ((lane >> 4) ? 8 : 0);
    const int b_kof = ((lane >> 3) & 1) * 8;

    const uint32_t a_base = sb + AS_T + a_row * ROWB + a_kof * 2;
    const uint32_t b_base0 = sb + (nw0 + b_nof) * ROWB + b_kof * 2;

    #pragma unroll
    for (int pass = 0; pass < 2; pass++) {
        const uint32_t b_base = b_base0 + ((pass == 0) ? WS_HI : WS_LO);
        #pragma unroll
        for (int ks = 0; ks < 8; ks++) {
            const int k0 = ks * 16;
            uint32_t af[2][4];
            ldsm_x4(a_base + k0 * 2,             af[0][0], af[0][1], af[0][2], af[0][3]);
            ldsm_x4(a_base + 16 * ROWB + k0 * 2, af[1][0], af[1][1], af[1][2], af[1][3]);
            uint32_t bf[8][2];
            #pragma unroll
            for (int p = 0; p < 4; p++) {
                uint32_t r0, r1, r2, r3;
                ldsm_x4(b_base + p * 16 * ROWB + k0 * 2, r0, r1, r2, r3);
                bf[2 * p][0] = r0; bf[2 * p][1] = r1;
                bf[2 * p + 1][0] = r2; bf[2 * p + 1][1] = r3;
            }
            #pragma unroll
            for (int i = 0; i < 2; i++)
                #pragma unroll
                for (int j = 0; j < 8; j++)
                    mma_f16(acc[i][j], af[i], bf[j]);
        }
    }

    // epilogue: fp32 (C) and/or fp16 (Ch)
    const int mq = lane >> 2;
    const int nq = (lane & 3) * 2;
    #pragma unroll
    for (int i = 0; i < 2; i++) {
        #pragma unroll
        for (int half = 0; half < 2; half++) {
            int gm = m0 + mw0 + i * 16 + mq + half * 8;
            if (gm < M) {
                #pragma unroll
                for (int j = 0; j < 8; j++) {
                    float2 o = half ? make_float2(acc[i][j][2], acc[i][j][3])
                                    : make_float2(acc[i][j][0], acc[i][j][1]);
                    if (C)
                        *reinterpret_cast<float2*>(C + (size_t)gm * CH + nw0 + j * 8 + nq) = o;
                    if (Ch) {
                        __half2 h = __float22half2_rn(o);
                        *reinterpret_cast<__half2*>(Ch + (size_t)gm * CH + nw0 + j * 8 + nq) = h;
                    }
                }
            }
        }
    }
}

// ---------------- aggr: warp-per-node; aggr_h[n] = t_h[n] - min_nbr t_h[col] ----------------
__global__ __launch_bounds__(256) void aggr_kernel(int N) {
    const int gw = (blockIdx.x * blockDim.x + threadIdx.x) >> 5;
    if (gw >= N) return;
    const int n = gw;
    const int lane = threadIdx.x & 31;
    const int cnt = min(g_cur[n], CAP);

    const __half2 hbig = __float2half2_rn(60000.f);
    __half2 a0 = hbig, a1 = hbig;
    __half2 b0 = hbig, b1 = hbig;

    const size_t csr_base = (size_t)n * CAP;

    for (int base = 0; base < cnt; base += 32) {
        int my_col = (base + lane < cnt) ? g_csr[csr_base + base + lane] : 0;
        int lim = min(32, cnt - base);
        int j = 0;
        #pragma unroll 4
        for (; j + 2 <= lim; j += 2) {
            int c0 = __shfl_sync(0xffffffffu, my_col, j);
            int c1 = __shfl_sync(0xffffffffu, my_col, j + 1);
            uint2 v0 = *reinterpret_cast<const uint2*>(g_t_h + (size_t)c0 * CH + lane * 4);
            uint2 v1 = *reinterpret_cast<const uint2*>(g_t_h + (size_t)c1 * CH + lane * 4);
            a0 = __hmin2(a0, *reinterpret_cast<const __half2*>(&v0.x));
            a1 = __hmin2(a1, *reinterpret_cast<const __half2*>(&v0.y));
            b0 = __hmin2(b0, *reinterpret_cast<const __half2*>(&v1.x));
            b1 = __hmin2(b1, *reinterpret_cast<const __half2*>(&v1.y));
        }
        if (j < lim) {
            int c0 = __shfl_sync(0xffffffffu, my_col, j);
            uint2 v0 = *reinterpret_cast<const uint2*>(g_t_h + (size_t)c0 * CH + lane * 4);
            a0 = __hmin2(a0, *reinterpret_cast<const __half2*>(&v0.x));
            a1 = __hmin2(a1, *reinterpret_cast<const __half2*>(&v0.y));
        }
    }

    // overflow spill (empty in practice; correct for any input)
    int novf = g_novf;
    for (int i = 0; i < novf; i++) {
        if (g_ovf_r[i] == n) {
            uint2 v = *reinterpret_cast<const uint2*>(g_t_h + (size_t)g_ovf_c[i] * CH + lane * 4);
            a0 = __hmin2(a0, *reinterpret_cast<const __half2*>(&v.x));
            a1 = __hmin2(a1, *reinterpret_cast<const __half2*>(&v.y));
        }
    }

    a0 = __hmin2(a0, b0);
    a1 = __hmin2(a1, b1);

    uint2 outv;
    if (cnt == 0) {
        __half2 z = __float2half2_rn(0.f);
        outv = make_uint2(*reinterpret_cast<uint32_t*>(&z), *reinterpret_cast<uint32_t*>(&z));
    } else {
        uint2 tv = *reinterpret_cast<const uint2*>(g_t_h + (size_t)n * CH + lane * 4);
        const __half2 t0 = *reinterpret_cast<const __half2*>(&tv.x);
        const __half2 t1 = *reinterpret_cast<const __half2*>(&tv.y);
        // fp32 subtract, round to fp16
        float2 d0 = make_float2(__low2float(t0) - __low2float(a0),
                                __high2float(t0) - __high2float(a0));
        float2 d1 = make_float2(__low2float(t1) - __low2float(a1),
                                __high2float(t1) - __high2float(a1));
        __half2 o0 = __float22half2_rn(d0);
        __half2 o1 = __float22half2_rn(d1);
        outv = make_uint2(*reinterpret_cast<uint32_t*>(&o0), *reinterpret_cast<uint32_t*>(&o1));
    }
    *reinterpret_cast<uint2*>(g_aggr_h + (size_t)n * CH + lane * 4) = outv;
}

// ---------------- launch: fork-join streams (scatter || gemm1) ----------------
extern "C" void kernel_launch(void* const* d_in, const int* in_sizes, int n_in,
                              void* d_out, int out_size) {
    const float* x  = (const float*)d_in[0];
    const int*   ei = (const int*)d_in[1];
    const float* Wt = (const float*)d_in[2];
    const float* Wp = (const float*)d_in[3];
    float* out = (float*)d_out;

    int N = in_sizes[0] / CH;
    int E = in_sizes[1] / 2;
    const int* row = ei;
    const int* col = ei + E;
    int ngb = (N + 127) / 128;

    void *pth = nullptr, *pah = nullptr;
    cudaGetSymbolAddress(&pth, g_t_h);
    cudaGetSymbolAddress(&pah, g_aggr_h);

    cudaFuncSetAttribute(tc_gemm_kernel, cudaFuncAttributeMaxDynamicSharedMemorySize, GSM_TOTAL);

    cudaStream_t s1;
    cudaStreamCreateWithFlags(&s1, cudaStreamNonBlocking);
    cudaEvent_t e_fork, e_join;
    cudaEventCreateWithFlags(&e_fork, cudaEventDisableTiming);
    cudaEventCreateWithFlags(&e_join, cudaEventDisableTiming);

    // init on default stream (zeroes g_cur, splits W)
    init_kernel<<<(N + 255) / 256, 256>>>(Wt, Wp, N);

    // fork: scatter on s1, gemm1 on default
    cudaEventRecord(e_fork, 0);
    cudaStreamWaitEvent(s1, e_fork, 0);
    scatter_kernel<<<((E + 3) / 4 + 255) / 256, 256, 0, s1>>>(row, col, E);
    tc_gemm_kernel<<<ngb, 256, GSM_TOTAL>>>(x, nullptr, nullptr, (__half*)pth, N, 0);

    // join: default stream waits for scatter
    cudaEventRecord(e_join, s1);
    cudaStreamWaitEvent(0, e_join, 0);

    aggr_kernel<<<(N * 32 + 255) / 256, 256>>>(N);
    tc_gemm_kernel<<<ngb, 256, GSM_TOTAL>>>(nullptr, (const __half*)pah, out, nullptr, N, 1);

    cudaEventDestroy(e_fork);
    cudaEventDestroy(e_join);
    cudaStreamDestroy(s1);
}

// round 16
// speedup vs baseline: 1.5413x; 1.1359x over previous
#include <cuda_runtime.h>
#include <cuda_fp16.h>
#include <cstdint>
#include <cstddef>

#define NMAX 100000
#define EMAX 3200000
#define CH 128
#define CAP 64           // padded-CSR slots per node
#define OVF_CAP 65536

// ---------------- scratch ----------------
__device__ __half g_t_h[(size_t)NMAX * CH];     // t = x @ W_theta^T (fp16)
__device__ __half g_aggr_h[(size_t)NMAX * CH];  // aggr output (fp16)
__device__ int    g_cur[NMAX];
__device__ int    g_csr[(size_t)NMAX * CAP];
__device__ int    g_novf;
__device__ int    g_ovf_r[OVF_CAP];
__device__ int    g_ovf_c[OVF_CAP];
__device__ __half g_w[2 * CH * CH];             // fp16 W (theta, phi)

// ---------------- init: zero counters + convert W to fp16 ----------------
__global__ void init_kernel(const float* __restrict__ Wt, const float* __restrict__ Wp, int n) {
    int i = blockIdx.x * blockDim.x + threadIdx.x;
    if (i < n) g_cur[i] = 0;
    if (i == 0) g_novf = 0;
    if (i < 2 * CH * CH) {
        float v = (i < CH * CH) ? Wt[i] : Wp[i - CH * CH];
        g_w[i] = __float2half_rn(v);
    }
}

// ---------------- padded-CSR scatter (4 edges/thread) ----------------
__device__ __forceinline__ void push_edge(int r, int c) {
    int p = atomicAdd(&g_cur[r], 1);
    if (p < CAP) {
        g_csr[(size_t)r * CAP + p] = c;
    } else {
        int o = atomicAdd(&g_novf, 1);
        if (o < OVF_CAP) { g_ovf_r[o] = r; g_ovf_c[o] = c; }
    }
}

__global__ void scatter_kernel(const int* __restrict__ row, const int* __restrict__ col, int E) {
    int t = blockIdx.x * blockDim.x + threadIdx.x;
    int e0 = t * 4;
    if (e0 >= E) return;
    if (((E & 3) == 0) && (e0 + 4 <= E)) {
        int4 r4 = *reinterpret_cast<const int4*>(row + e0);
        int4 c4 = *reinterpret_cast<const int4*>(col + e0);
        push_edge(r4.x, c4.x);
        push_edge(r4.y, c4.y);
        push_edge(r4.z, c4.z);
        push_edge(r4.w, c4.w);
    } else {
        int lim = min(e0 + 4, E);
        for (int e = e0; e < lim; e++) push_edge(row[e], col[e]);
    }
}

// ---------------- HMMA helpers ----------------
__device__ __forceinline__ uint32_t smem_u32(const void* p) {
    uint32_t a;
    asm("{ .reg .u64 t; cvta.to.shared.u64 t, %1; cvt.u32.u64 %0, t; }" : "=r"(a) : "l"(p));
    return a;
}

__device__ __forceinline__ void ldsm_x4(uint32_t addr, uint32_t& r0, uint32_t& r1,
                                        uint32_t& r2, uint32_t& r3) {
    asm volatile("ldmatrix.sync.aligned.m8n8.x4.shared.b16 {%0,%1,%2,%3}, [%4];"
                 : "=r"(r0), "=r"(r1), "=r"(r2), "=r"(r3) : "r"(addr));
}

__device__ __forceinline__ void mma_f16(float* c, const uint32_t* a, const uint32_t* b) {
    asm volatile(
        "mma.sync.aligned.m16n8k16.row.col.f32.f16.f16.f32 "
        "{%0,%1,%2,%3}, {%4,%5,%6,%7}, {%8,%9}, {%0,%1,%2,%3};"
        : "+f"(c[0]), "+f"(c[1]), "+f"(c[2]), "+f"(c[3])
        : "r"(a[0]), "r"(a[1]), "r"(a[2]), "r"(a[3]), "r"(b[0]), "r"(b[1]));
}

// ---------------- tensor-core GEMM: C[M,128] = A[M,128] @ W^T ----------------
// Pure fp16 operands, single MMA pass. SMEM: A tile + W tile (2 CTAs/SM).
#define ROWB 272
#define TILEB (128 * ROWB)
#define AS_T  0
#define WS_T  TILEB
#define GSM_TOTAL (2 * TILEB)     // 69632

__global__ __launch_bounds__(256, 2) void tc_gemm_kernel(
    const float* __restrict__ A32, const __half* __restrict__ A16,
    float* __restrict__ C, __half* __restrict__ Ch,
    int M, int which)
{
    extern __shared__ char smem[];
    const uint32_t sb = smem_u32(smem);
    const int tid = threadIdx.x;
    const int w = tid >> 5;
    const int lane = tid & 31;
    const int m0 = blockIdx.x * 128;

    // stage A -> fp16 smem tile
    if (A32) {
        #pragma unroll
        for (int it = 0; it < 16; it++) {
            int q = tid + it * 256;          // 0..4095 float4s
            int r = q >> 5;
            int c4 = q & 31;
            int gm = m0 + r;
            float4 v = make_float4(0.f, 0.f, 0.f, 0.f);
            if (gm < M) v = *reinterpret_cast<const float4*>(A32 + (size_t)gm * CH + c4 * 4);
            __half2 h01 = __float22half2_rn(make_float2(v.x, v.y));
            __half2 h23 = __float22half2_rn(make_float2(v.z, v.w));
            int off = r * ROWB + c4 * 8;
            *reinterpret_cast<uint2*>(smem + AS_T + off) =
                make_uint2(*reinterpret_cast<uint32_t*>(&h01), *reinterpret_cast<uint32_t*>(&h23));
        }
    } else {
        #pragma unroll
        for (int it = 0; it < 8; it++) {
            int q = tid + it * 256;          // 0..2047 uint4s (16B = 8 halves)
            int r = q >> 4;
            int u = q & 15;
            int gm = m0 + r;
            uint4 v = make_uint4(0u, 0u, 0u, 0u);
            if (gm < M) v = *reinterpret_cast<const uint4*>(A16 + (size_t)gm * CH + u * 8);
            *reinterpret_cast<uint4*>(smem + AS_T + r * ROWB + u * 16) = v;
        }
    }

    // stage W (fp16 in global)
    const uint4* wsrc = reinterpret_cast<const uint4*>(g_w + (size_t)which * CH * CH);
    #pragma unroll
    for (int it = 0; it < 8; it++) {
        int q = tid + it * 256;
        int r = q >> 4;
        int u = q & 15;
        *reinterpret_cast<uint4*>(smem + WS_T + r * ROWB + u * 16) = wsrc[q];
    }
    __syncthreads();

    // compute: warp grid 4(M) x 2(N); warp tile 32x64; single pass
    const int mw0 = (w & 3) * 32;
    const int nw0 = (w >> 2) * 64;

    float acc[2][8][4];
    #pragma unroll
    for (int i = 0; i < 2; i++)
        #pragma unroll
        for (int j = 0; j < 8; j++)
            #pragma unroll
            for (int q = 0; q < 4; q++) acc[i][j][q] = 0.f;

    const int a_row = mw0 + (lane & 15);
    const int a_kof = (lane >> 4) * 8;
    const int b_nof = (lane & 7) + ((lane >> 4) ? 8 : 0);
    const int b_kof = ((lane >> 3) & 1) * 8;

    const uint32_t a_base = sb + AS_T + a_row * ROWB + a_kof * 2;
    const uint32_t b_base = sb + WS_T + (nw0 + b_nof) * ROWB + b_kof * 2;

    #pragma unroll
    for (int ks = 0; ks < 8; ks++) {
        const int k0 = ks * 16;
        uint32_t af[2][4];
        ldsm_x4(a_base + k0 * 2,             af[0][0], af[0][1], af[0][2], af[0][3]);
        ldsm_x4(a_base + 16 * ROWB + k0 * 2, af[1][0], af[1][1], af[1][2], af[1][3]);
        uint32_t bf[8][2];
        #pragma unroll
        for (int p = 0; p < 4; p++) {
            uint32_t r0, r1, r2, r3;
            ldsm_x4(b_base + p * 16 * ROWB + k0 * 2, r0, r1, r2, r3);
            bf[2 * p][0] = r0; bf[2 * p][1] = r1;
            bf[2 * p + 1][0] = r2; bf[2 * p + 1][1] = r3;
        }
        #pragma unroll
        for (int i = 0; i < 2; i++)
            #pragma unroll
            for (int j = 0; j < 8; j++)
                mma_f16(acc[i][j], af[i], bf[j]);
    }

    // epilogue: fp32 (C) and/or fp16 (Ch)
    const int mq = lane >> 2;
    const int nq = (lane & 3) * 2;
    #pragma unroll
    for (int i = 0; i < 2; i++) {
        #pragma unroll
        for (int half = 0; half < 2; half++) {
            int gm = m0 + mw0 + i * 16 + mq + half * 8;
            if (gm < M) {
                #pragma unroll
                for (int j = 0; j < 8; j++) {
                    float2 o = half ? make_float2(acc[i][j][2], acc[i][j][3])
                                    : make_float2(acc[i][j][0], acc[i][j][1]);
                    if (C)
                        *reinterpret_cast<float2*>(C + (size_t)gm * CH + nw0 + j * 8 + nq) = o;
                    if (Ch) {
                        __half2 h = __float22half2_rn(o);
                        *reinterpret_cast<__half2*>(Ch + (size_t)gm * CH + nw0 + j * 8 + nq) = h;
                    }
                }
            }
        }
    }
}

// ---------------- aggr: warp-per-node; aggr_h[n] = t_h[n] - min_nbr t_h[col] ----------------
__global__ __launch_bounds__(256) void aggr_kernel(int N) {
    const int gw = (blockIdx.x * blockDim.x + threadIdx.x) >> 5;
    if (gw >= N) return;
    const int n = gw;
    const int lane = threadIdx.x & 31;
    const int cnt = min(g_cur[n], CAP);

    const __half2 hbig = __float2half2_rn(60000.f);
    __half2 a0 = hbig, a1 = hbig;
    __half2 b0 = hbig, b1 = hbig;

    const size_t csr_base = (size_t)n * CAP;

    for (int base = 0; base < cnt; base += 32) {
        int my_col = (base + lane < cnt) ? g_csr[csr_base + base + lane] : 0;
        int lim = min(32, cnt - base);
        int j = 0;
        #pragma unroll 4
        for (; j + 2 <= lim; j += 2) {
            int c0 = __shfl_sync(0xffffffffu, my_col, j);
            int c1 = __shfl_sync(0xffffffffu, my_col, j + 1);
            uint2 v0 = *reinterpret_cast<const uint2*>(g_t_h + (size_t)c0 * CH + lane * 4);
            uint2 v1 = *reinterpret_cast<const uint2*>(g_t_h + (size_t)c1 * CH + lane * 4);
            a0 = __hmin2(a0, *reinterpret_cast<const __half2*>(&v0.x));
            a1 = __hmin2(a1, *reinterpret_cast<const __half2*>(&v0.y));
            b0 = __hmin2(b0, *reinterpret_cast<const __half2*>(&v1.x));
            b1 = __hmin2(b1, *reinterpret_cast<const __half2*>(&v1.y));
        }
        if (j < lim) {
            int c0 = __shfl_sync(0xffffffffu, my_col, j);
            uint2 v0 = *reinterpret_cast<const uint2*>(g_t_h + (size_t)c0 * CH + lane * 4);
            a0 = __hmin2(a0, *reinterpret_cast<const __half2*>(&v0.x));
            a1 = __hmin2(a1, *reinterpret_cast<const __half2*>(&v0.y));
        }
    }

    // overflow spill (empty in practice; correct for any input)
    int novf = g_novf;
    for (int i = 0; i < novf; i++) {
        if (g_ovf_r[i] == n) {
            uint2 v = *reinterpret_cast<const uint2*>(g_t_h + (size_t)g_ovf_c[i] * CH + lane * 4);
            a0 = __hmin2(a0, *reinterpret_cast<const __half2*>(&v.x));
            a1 = __hmin2(a1, *reinterpret_cast<const __half2*>(&v.y));
        }
    }

    a0 = __hmin2(a0, b0);
    a1 = __hmin2(a1, b1);

    uint2 outv;
    if (cnt == 0) {
        __half2 z = __float2half2_rn(0.f);
        outv = make_uint2(*reinterpret_cast<uint32_t*>(&z), *reinterpret_cast<uint32_t*>(&z));
    } else {
        uint2 tv = *reinterpret_cast<const uint2*>(g_t_h + (size_t)n * CH + lane * 4);
        const __half2 t0 = *reinterpret_cast<const __half2*>(&tv.x);
        const __half2 t1 = *reinterpret_cast<const __half2*>(&tv.y);
        float2 d0 = make_float2(__low2float(t0) - __low2float(a0),
                                __high2float(t0) - __high2float(a0));
        float2 d1 = make_float2(__low2float(t1) - __low2float(a1),
                                __high2float(t1) - __high2float(a1));
        __half2 o0 = __float22half2_rn(d0);
        __half2 o1 = __float22half2_rn(d1);
        outv = make_uint2(*reinterpret_cast<uint32_t*>(&o0), *reinterpret_cast<uint32_t*>(&o1));
    }
    *reinterpret_cast<uint2*>(g_aggr_h + (size_t)n * CH + lane * 4) = outv;
}

// ---------------- launch: fork-join streams (scatter || gemm1) ----------------
extern "C" void kernel_launch(void* const* d_in, const int* in_sizes, int n_in,
                              void* d_out, int out_size) {
    const float* x  = (const float*)d_in[0];
    const int*   ei = (const int*)d_in[1];
    const float* Wt = (const float*)d_in[2];
    const float* Wp = (const float*)d_in[3];
    float* out = (float*)d_out;

    int N = in_sizes[0] / CH;
    int E = in_sizes[1] / 2;
    const int* row = ei;
    const int* col = ei + E;
    int ngb = (N + 127) / 128;

    void *pth = nullptr, *pah = nullptr;
    cudaGetSymbolAddress(&pth, g_t_h);
    cudaGetSymbolAddress(&pah, g_aggr_h);

    cudaFuncSetAttribute(tc_gemm_kernel, cudaFuncAttributeMaxDynamicSharedMemorySize, GSM_TOTAL);

    cudaStream_t s1;
    cudaStreamCreateWithFlags(&s1, cudaStreamNonBlocking);
    cudaEvent_t e_fork, e_join;
    cudaEventCreateWithFlags(&e_fork, cudaEventDisableTiming);
    cudaEventCreateWithFlags(&e_join, cudaEventDisableTiming);

    // init on default stream (zeroes g_cur, converts W)
    init_kernel<<<(N + 255) / 256, 256>>>(Wt, Wp, N);

    // fork: scatter on s1, gemm1 on default
    cudaEventRecord(e_fork, 0);
    cudaStreamWaitEvent(s1, e_fork, 0);
    scatter_kernel<<<((E + 3) / 4 + 255) / 256, 256, 0, s1>>>(row, col, E);
    tc_gemm_kernel<<<ngb, 256, GSM_TOTAL>>>(x, nullptr, nullptr, (__half*)pth, N, 0);

    // join: default stream waits for scatter
    cudaEventRecord(e_join, s1);
    cudaStreamWaitEvent(0, e_join, 0);

    aggr_kernel<<<(N * 32 + 255) / 256, 256>>>(N);
    tc_gemm_kernel<<<ngb, 256, GSM_TOTAL>>>(nullptr, (const __half*)pah, out, nullptr, N, 1);

    cudaEventDestroy(e_fork);
    cudaEventDestroy(e_join);
    cudaStreamDestroy(s1);
}